// round 1
// baseline (speedup 1.0000x reference)
#include <cuda_runtime.h>

#define EPSV 1e-7f
#define NPOS 288     // 2*12*12 output positions
#define KKI  288     // 3*3*32 input votes
#define NC   32
#define PP   16
#define NTH  256
#define NWARP 8
#define IPW  36      // KKI / NWARP

// Scratch: W re-laid out as Wre[i][c][r][q] (q fastest) for float4 loads.
__device__ float g_Wre[KKI * NC * PP];

__global__ void relayout_W_kernel(const float* __restrict__ W) {
    int idx = blockIdx.x * 256 + threadIdx.x;
    if (idx < KKI * NC * PP) {
        int r  = idx & 3;
        int q  = (idx >> 2) & 3;
        int ic = idx >> 4;
        g_Wre[(ic << 4) + (r << 2) + q] = W[idx];
    }
}

__device__ __forceinline__ float dot4(float4 a, float4 b) {
    return fmaf(a.x, b.x, fmaf(a.y, b.y, fmaf(a.z, b.z, a.w * b.w)));
}

// Compute V[i, c, 0..15] for this thread's capsule c: v[p*4+r] = sum_q Mp[i,p,q]*W[i,c,q,r]
__device__ __forceinline__ void compute_v(const float* __restrict__ sMp, int i, int c, float v[16]) {
    const float4* mp = reinterpret_cast<const float4*>(sMp + i * 16);
    float4 m0 = mp[0], m1 = mp[1], m2 = mp[2], m3 = mp[3];
    const float4* wp = reinterpret_cast<const float4*>(g_Wre + (i * NC + c) * 16);
    float4 w0 = wp[0], w1 = wp[1], w2 = wp[2], w3 = wp[3];
    v[0]  = dot4(m0, w0); v[1]  = dot4(m0, w1); v[2]  = dot4(m0, w2); v[3]  = dot4(m0, w3);
    v[4]  = dot4(m1, w0); v[5]  = dot4(m1, w1); v[6]  = dot4(m1, w2); v[7]  = dot4(m1, w3);
    v[8]  = dot4(m2, w0); v[9]  = dot4(m2, w1); v[10] = dot4(m2, w2); v[11] = dot4(m2, w3);
    v[12] = dot4(m3, w0); v[13] = dot4(m3, w1); v[14] = dot4(m3, w2); v[15] = dot4(m3, w3);
}

// Per-iteration statistics: M, stdv-derived weights, base for log_p, activation a_j.
// All 32 lanes of every warp execute (lane = capsule c); warp-redundant but cheap.
__device__ __forceinline__ void compute_stats(
    const float* __restrict__ sAcc, const float* __restrict__ sS1, const float* __restrict__ sS2,
    int c, float rscale, float bv, float ba, float inv_temp,
    float M[16], float wgt[16], float& base, float& aj)
{
    float RsRaw = sAcc[c * 17 + 16];
    float Rs = RsRaw * rscale;               // rscale folds the uniform R=1/NC of iter 0
    float invR = 1.0f / RsRaw;
    float sumlog = 0.0f;
    #pragma unroll
    for (int k = 0; k < 16; k++) {
        float m   = sAcc[c * 17 + k] * invR;
        float var = sS2[c * 17 + k] - 2.0f * m * sS1[c * 17 + k] + 288.0f * m * m;
        var = fmaxf(var, 0.0f);
        float sd = sqrtf(var);
        sumlog += logf(sd + EPSV);
        wgt[k] = 0.5f / (sd * sd);           // 1/(2*stdv^2)
        M[k]   = m;
    }
    float cost = (16.0f * bv + sumlog) * Rs;
    // mean over capsules (warp lanes)
    float s = cost;
    #pragma unroll
    for (int o = 16; o >= 1; o >>= 1) s += __shfl_xor_sync(0xffffffffu, s, o);
    float cmean = s * (1.0f / 32.0f);
    float d = cost - cmean;
    float sq = d * d;
    #pragma unroll
    for (int o = 16; o >= 1; o >>= 1) sq += __shfl_xor_sync(0xffffffffu, sq, o);
    float cstd  = sqrtf(sq * (1.0f / 32.0f));
    float acost = ba + (cmean - cost) / (cstd + EPSV);
    aj   = 1.0f / (1.0f + expf(-inv_temp * acost));
    base = logf(aj + EPSV) - sumlog;
}

__global__ __launch_bounds__(NTH, 2)
void caps_em_kernel(const float* __restrict__ x,
                    const float* __restrict__ beta_v,
                    const float* __restrict__ beta_a,
                    float* __restrict__ out)
{
    __shared__ float sMp[KKI * 16];   // patch pose matrices
    __shared__ float sA[KKI];         // patch activations a_i
    __shared__ float sAcc[NC * 17];   // Mnum[c][0..15], Rsum at [c][16]
    __shared__ float sS1[NC * 17];    // sum V   (iteration-invariant)
    __shared__ float sS2[NC * 17];    // sum V^2 (iteration-invariant)

    const int tid  = threadIdx.x;
    const int lane = tid & 31;        // capsule c
    const int wid  = tid >> 5;
    const int c    = lane;
    const int pos  = blockIdx.x;
    const int b  = pos / 144;
    const int rp = pos % 144;
    const int ho = rp / 12, wo = rp % 12;

    // ---- load patch: i = (ki*3+kj)*32 + cin ----
    for (int i = tid; i < KKI; i += NTH) {
        int kk = i >> 5, cin = i & 31;
        int ki = kk / 3, kj = kk % 3;
        const float* src = x + ((((b * 14) + ho + ki) * 14 + (wo + kj)) * 32 + cin) * 17;
        #pragma unroll
        for (int e = 0; e < 16; e++) sMp[i * 16 + e] = src[e];
        sA[i] = src[16];
    }
    for (int j = tid; j < NC * 17; j += NTH) { sAcc[j] = 0.0f; sS1[j] = 0.0f; sS2[j] = 0.0f; }
    __syncthreads();

    const float bv = beta_v[c];
    const float ba = beta_a[c];
    const int i0 = wid * IPW, i1 = i0 + IPW;

    // ================= PASS 1: iter 0 (uniform R) + S1/S2 =================
    {
        float Mnum[16], S1[16], S2[16];
        float Rsum = 0.0f;
        #pragma unroll
        for (int k = 0; k < 16; k++) { Mnum[k] = 0.0f; S1[k] = 0.0f; S2[k] = 0.0f; }
        #pragma unroll 2
        for (int i = i0; i < i1; i++) {
            float v[16];
            compute_v(sMp, i, c, v);
            float ai = sA[i];
            #pragma unroll
            for (int k = 0; k < 16; k++) {
                S1[k] += v[k];
                S2[k]  = fmaf(v[k], v[k], S2[k]);
                Mnum[k] = fmaf(ai, v[k], Mnum[k]);
            }
            Rsum += ai;
        }
        #pragma unroll
        for (int k = 0; k < 16; k++) {
            atomicAdd(&sAcc[c * 17 + k], Mnum[k]);
            atomicAdd(&sS1[c * 17 + k], S1[k]);
            atomicAdd(&sS2[c * 17 + k], S2[k]);
        }
        atomicAdd(&sAcc[c * 17 + 16], Rsum);
    }
    __syncthreads();

    float M[16], wgt[16], base, aj;
    compute_stats(sAcc, sS1, sS2, c, 1.0f / 32.0f, bv, ba, 1.0f, M, wgt, base, aj);
    __syncthreads();
    for (int j = tid; j < NC * 17; j += NTH) sAcc[j] = 0.0f;
    __syncthreads();

    // ================= PASS 2 & 3: routing iterations 1, 2 =================
    #pragma unroll 1
    for (int it = 1; it <= 2; it++) {
        float Mnum[16];
        float Rsum = 0.0f;
        #pragma unroll
        for (int k = 0; k < 16; k++) Mnum[k] = 0.0f;

        #pragma unroll 2
        for (int i = i0; i < i1; i++) {
            float v[16];
            compute_v(sMp, i, c, v);
            float e = 0.0f;
            #pragma unroll
            for (int k = 0; k < 16; k++) {
                float d = v[k] - M[k];
                e = fmaf(d * wgt[k], d, e);
            }
            float lp = base - e;
            // softmax over capsules (lanes)
            float mx = lp;
            #pragma unroll
            for (int o = 16; o >= 1; o >>= 1) mx = fmaxf(mx, __shfl_xor_sync(0xffffffffu, mx, o));
            float ex = __expf(lp - mx);
            float sm = ex;
            #pragma unroll
            for (int o = 16; o >= 1; o >>= 1) sm += __shfl_xor_sync(0xffffffffu, sm, o);
            float Rw = sA[i] * __fdividef(ex, sm);
            Rsum += Rw;
            #pragma unroll
            for (int k = 0; k < 16; k++) Mnum[k] = fmaf(Rw, v[k], Mnum[k]);
        }
        #pragma unroll
        for (int k = 0; k < 16; k++) atomicAdd(&sAcc[c * 17 + k], Mnum[k]);
        atomicAdd(&sAcc[c * 17 + 16], Rsum);
        __syncthreads();

        compute_stats(sAcc, sS1, sS2, c, 1.0f, bv, ba, 1.0f + (float)it, M, wgt, base, aj);
        if (it < 2) {
            __syncthreads();
            for (int j = tid; j < NC * 17; j += NTH) sAcc[j] = 0.0f;
            __syncthreads();
        }
    }

    // ---- write output: [pos][c][0..15] = M, [16] = sigmoid(a_j) ----
    if (wid == 0) {
        float* dst = out + (pos * NC + c) * 17;
        #pragma unroll
        for (int k = 0; k < 16; k++) dst[k] = M[k];
        dst[16] = 1.0f / (1.0f + expf(-aj));
    }
}

extern "C" void kernel_launch(void* const* d_in, const int* in_sizes, int n_in,
                              void* d_out, int out_size) {
    const float* x      = (const float*)d_in[0];
    const float* W      = (const float*)d_in[1];
    const float* beta_v = (const float*)d_in[2];
    const float* beta_a = (const float*)d_in[3];
    float* out = (float*)d_out;

    relayout_W_kernel<<<(KKI * NC * PP + 255) / 256, 256>>>(W);
    caps_em_kernel<<<NPOS, NTH>>>(x, beta_v, beta_a, out);
}

// round 3
// speedup vs baseline: 1.0264x; 1.0264x over previous
#include <cuda_runtime.h>

#define EPSV 1e-7f
#define NPOS 288     // 2*12*12 output positions
#define KKI  288     // 3*3*32 input votes
#define NC   32
#define PP   16
#define NTH  256
#define NWARP 8
#define IPW  36      // KKI / NWARP

// Scratch: W re-laid out as Wre[i][c][r][q] (q fastest) for float4 loads.
__device__ float g_Wre[KKI * NC * PP];

__global__ void relayout_W_kernel(const float* __restrict__ W) {
    int idx = blockIdx.x * 256 + threadIdx.x;
    if (idx < KKI * NC * PP) {
        int r  = idx & 3;
        int q  = (idx >> 2) & 3;
        int ic = idx >> 4;
        g_Wre[(ic << 4) + (r << 2) + q] = W[idx];
    }
}

__device__ __forceinline__ float dot4(float4 a, float4 b) {
    return fmaf(a.x, b.x, fmaf(a.y, b.y, fmaf(a.z, b.z, a.w * b.w)));
}

// Compute V[i, c, 0..15] for this thread's capsule c
__device__ __forceinline__ void compute_v(const float* __restrict__ sMp, int i, int c, float v[16]) {
    const float4* mp = reinterpret_cast<const float4*>(sMp + i * 16);
    float4 m0 = mp[0], m1 = mp[1], m2 = mp[2], m3 = mp[3];
    const float4* wp = reinterpret_cast<const float4*>(g_Wre + (i * NC + c) * 16);
    float4 w0 = wp[0], w1 = wp[1], w2 = wp[2], w3 = wp[3];
    v[0]  = dot4(m0, w0); v[1]  = dot4(m0, w1); v[2]  = dot4(m0, w2); v[3]  = dot4(m0, w3);
    v[4]  = dot4(m1, w0); v[5]  = dot4(m1, w1); v[6]  = dot4(m1, w2); v[7]  = dot4(m1, w3);
    v[8]  = dot4(m2, w0); v[9]  = dot4(m2, w1); v[10] = dot4(m2, w2); v[11] = dot4(m2, w3);
    v[12] = dot4(m3, w0); v[13] = dot4(m3, w1); v[14] = dot4(m3, w2); v[15] = dot4(m3, w3);
}

// Per-iteration statistics. sRedM: Mnum[c][0..15], Rsum at [c][16] (stride 17).
// sRedS: S1 at [c*33 + k], S2 at [c*33 + 16 + k] (stride 33, conflict-free).
__device__ __forceinline__ void compute_stats(
    const float* __restrict__ sRedM, const float* __restrict__ sRedS,
    int c, float rscale, float bv, float ba, float inv_temp,
    float M[16], float wgt[16], float& base, float& aj)
{
    float RsRaw = sRedM[c * 17 + 16];
    float Rs = RsRaw * rscale;               // rscale folds the uniform R=1/NC of iter 0
    float invR = 1.0f / RsRaw;
    float sumlog = 0.0f;
    #pragma unroll
    for (int k = 0; k < 16; k++) {
        float m   = sRedM[c * 17 + k] * invR;
        float s1  = sRedS[c * 33 + k];
        float s2  = sRedS[c * 33 + 16 + k];
        float var = s2 - 2.0f * m * s1 + 288.0f * m * m;
        var = fmaxf(var, 0.0f);
        float sd = sqrtf(var);
        sumlog += logf(sd + EPSV);
        wgt[k] = 0.5f / (sd * sd);           // 1/(2*stdv^2)
        M[k]   = m;
    }
    float cost = (16.0f * bv + sumlog) * Rs;
    float s = cost;
    #pragma unroll
    for (int o = 16; o >= 1; o >>= 1) s += __shfl_xor_sync(0xffffffffu, s, o);
    float cmean = s * (1.0f / 32.0f);
    float d = cost - cmean;
    float sq = d * d;
    #pragma unroll
    for (int o = 16; o >= 1; o >>= 1) sq += __shfl_xor_sync(0xffffffffu, sq, o);
    float cstd  = sqrtf(sq * (1.0f / 32.0f));
    float acost = ba + (cmean - cost) / (cstd + EPSV);
    aj   = 1.0f / (1.0f + expf(-inv_temp * acost));
    base = logf(aj + EPSV) - sumlog;
}

__global__ __launch_bounds__(NTH, 2)
void caps_em_kernel(const float* __restrict__ x,
                    const float* __restrict__ beta_v,
                    const float* __restrict__ beta_a,
                    float* __restrict__ out)
{
    __shared__ float sMp[KKI * 16];          // 4608 floats
    __shared__ float sA[KKI];                // 288
    __shared__ float sPart[NWARP * NC * 17]; // 4352 (per-warp staging, stride 17)
    __shared__ float sRedM[NC * 17];         // 544
    __shared__ float sRedS[NC * 33];         // 1056

    const int tid  = threadIdx.x;
    const int lane = tid & 31;        // capsule c
    const int wid  = tid >> 5;
    const int c    = lane;
    const int pos  = blockIdx.x;
    const int b  = pos / 144;
    const int rp = pos % 144;
    const int ho = rp / 12, wo = rp % 12;

    // ---- load patch: i = (ki*3+kj)*32 + cin ----
    for (int i = tid; i < KKI; i += NTH) {
        int kk = i >> 5, cin = i & 31;
        int ki = kk / 3, kj = kk % 3;
        const float* src = x + ((((b * 14) + ho + ki) * 14 + (wo + kj)) * 32 + cin) * 17;
        #pragma unroll
        for (int e = 0; e < 16; e++) sMp[i * 16 + e] = src[e];
        sA[i] = src[16];
    }
    __syncthreads();

    const float bv = beta_v[c];
    const float ba = beta_a[c];
    const int i0 = wid * IPW, i1 = i0 + IPW;
    float* myP = sPart + (wid * NC + c) * 17;

    // ================= PASS 1: iter 0 (uniform R) + S1/S2 =================
    {
        float Mnum[16], S1[16], S2[16];
        float Rsum = 0.0f;
        #pragma unroll
        for (int k = 0; k < 16; k++) { Mnum[k] = 0.0f; S1[k] = 0.0f; S2[k] = 0.0f; }
        #pragma unroll 2
        for (int i = i0; i < i1; i++) {
            float v[16];
            compute_v(sMp, i, c, v);
            float ai = sA[i];
            #pragma unroll
            for (int k = 0; k < 16; k++) {
                S1[k] += v[k];
                S2[k]  = fmaf(v[k], v[k], S2[k]);
                Mnum[k] = fmaf(ai, v[k], Mnum[k]);
            }
            Rsum += ai;
        }
        // --- round A: Mnum + Rsum ---
        #pragma unroll
        for (int k = 0; k < 16; k++) myP[k] = Mnum[k];
        myP[16] = Rsum;
        __syncthreads();
        for (int s = tid; s < NC * 17; s += NTH) {
            float acc = 0.0f;
            #pragma unroll
            for (int w = 0; w < NWARP; w++) acc += sPart[w * (NC * 17) + s];
            sRedM[s] = acc;
        }
        __syncthreads();
        // --- round B: S1 ---
        #pragma unroll
        for (int k = 0; k < 16; k++) myP[k] = S1[k];
        __syncthreads();
        for (int s = tid; s < NC * 17; s += NTH) {
            int cc = s / 17, kk = s - cc * 17;
            if (kk < 16) {
                float acc = 0.0f;
                #pragma unroll
                for (int w = 0; w < NWARP; w++) acc += sPart[w * (NC * 17) + s];
                sRedS[cc * 33 + kk] = acc;
            }
        }
        __syncthreads();
        // --- round C: S2 ---
        #pragma unroll
        for (int k = 0; k < 16; k++) myP[k] = S2[k];
        __syncthreads();
        for (int s = tid; s < NC * 17; s += NTH) {
            int cc = s / 17, kk = s - cc * 17;
            if (kk < 16) {
                float acc = 0.0f;
                #pragma unroll
                for (int w = 0; w < NWARP; w++) acc += sPart[w * (NC * 17) + s];
                sRedS[cc * 33 + 16 + kk] = acc;
            }
        }
        __syncthreads();
    }

    float M[16], wgt[16], base, aj;
    compute_stats(sRedM, sRedS, c, 1.0f / 32.0f, bv, ba, 1.0f, M, wgt, base, aj);

    // ================= PASS 2 & 3: routing iterations 1, 2 =================
    #pragma unroll 1
    for (int it = 1; it <= 2; it++) {
        float Mnum[16];
        float Rsum = 0.0f;
        #pragma unroll
        for (int k = 0; k < 16; k++) Mnum[k] = 0.0f;

        #pragma unroll 2
        for (int i = i0; i < i1; i++) {
            float v[16];
            compute_v(sMp, i, c, v);
            float e = 0.0f;
            #pragma unroll
            for (int k = 0; k < 16; k++) {
                float d = v[k] - M[k];
                e = fmaf(d * wgt[k], d, e);
            }
            float lp = base - e;
            // softmax over capsules (lanes)
            float mx = lp;
            #pragma unroll
            for (int o = 16; o >= 1; o >>= 1) mx = fmaxf(mx, __shfl_xor_sync(0xffffffffu, mx, o));
            float ex = __expf(lp - mx);
            float sm = ex;
            #pragma unroll
            for (int o = 16; o >= 1; o >>= 1) sm += __shfl_xor_sync(0xffffffffu, sm, o);
            float Rw = sA[i] * __fdividef(ex, sm);
            Rsum += Rw;
            #pragma unroll
            for (int k = 0; k < 16; k++) Mnum[k] = fmaf(Rw, v[k], Mnum[k]);
        }
        __syncthreads();  // protect sPart reuse from previous round's readers
        #pragma unroll
        for (int k = 0; k < 16; k++) myP[k] = Mnum[k];
        myP[16] = Rsum;
        __syncthreads();
        for (int s = tid; s < NC * 17; s += NTH) {
            float acc = 0.0f;
            #pragma unroll
            for (int w = 0; w < NWARP; w++) acc += sPart[w * (NC * 17) + s];
            sRedM[s] = acc;
        }
        __syncthreads();

        compute_stats(sRedM, sRedS, c, 1.0f, bv, ba, 1.0f + (float)it, M, wgt, base, aj);
    }

    // ---- write output: [pos][c][0..15] = M, [16] = sigmoid(a_j) ----
    if (wid == 0) {
        float* dst = out + (pos * NC + c) * 17;
        #pragma unroll
        for (int k = 0; k < 16; k++) dst[k] = M[k];
        dst[16] = 1.0f / (1.0f + expf(-aj));
    }
}

extern "C" void kernel_launch(void* const* d_in, const int* in_sizes, int n_in,
                              void* d_out, int out_size) {
    const float* x      = (const float*)d_in[0];
    const float* W      = (const float*)d_in[1];
    const float* beta_v = (const float*)d_in[2];
    const float* beta_a = (const float*)d_in[3];
    float* out = (float*)d_out;

    relayout_W_kernel<<<(KKI * NC * PP + 255) / 256, 256>>>(W);
    caps_em_kernel<<<NPOS, NTH>>>(x, beta_v, beta_a, out);
}

// round 4
// speedup vs baseline: 1.3450x; 1.3104x over previous
#include <cuda_runtime.h>

#define EPSV 1e-7f
#define NPOS 288     // 2*12*12 output positions
#define KKI  288     // 3*3*32 input votes
#define NC   32
#define PP   16
#define NTH  256
#define NWARP 8
#define IPW  36      // KKI / NWARP

// W re-laid out chunk-major for coalesced warp loads:
// g_W2[i][j][c][q]  (j = output-column chunk r, c = capsule, q fastest)
// index = ((i*4 + j)*32 + c)*4 + q = i*512 + j*128 + c*4 + q
__device__ float g_W2[KKI * NC * PP];

__global__ void relayout_W_kernel(const float* __restrict__ W) {
    int o = blockIdx.x * 256 + threadIdx.x;
    if (o < KKI * NC * PP) {
        int q = o & 3;
        int c = (o >> 2) & 31;
        int j = (o >> 7) & 3;
        int i = o >> 9;
        // original: W[((i*32 + c)*4 + q)*4 + j]
        g_W2[o] = W[i * 512 + c * 16 + q * 4 + j];
    }
}

__device__ __forceinline__ float dot4(float4 a, float4 b) {
    return fmaf(a.x, b.x, fmaf(a.y, b.y, fmaf(a.z, b.z, a.w * b.w)));
}

// Compute V[i, c, 0..15] for this thread's capsule c.
// Coalesced: LDG #j reads 512 contiguous bytes across the warp (4 wavefronts).
__device__ __forceinline__ void compute_v(const float* __restrict__ sMp, int i, int c, float v[16]) {
    const float4* mp = reinterpret_cast<const float4*>(sMp + i * 16);
    float4 m0 = mp[0], m1 = mp[1], m2 = mp[2], m3 = mp[3];
    const float4* wp = reinterpret_cast<const float4*>(g_W2 + i * 512) + c;
    float4 w0 = wp[0], w1 = wp[32], w2 = wp[64], w3 = wp[96];
    v[0]  = dot4(m0, w0); v[1]  = dot4(m0, w1); v[2]  = dot4(m0, w2); v[3]  = dot4(m0, w3);
    v[4]  = dot4(m1, w0); v[5]  = dot4(m1, w1); v[6]  = dot4(m1, w2); v[7]  = dot4(m1, w3);
    v[8]  = dot4(m2, w0); v[9]  = dot4(m2, w1); v[10] = dot4(m2, w2); v[11] = dot4(m2, w3);
    v[12] = dot4(m3, w0); v[13] = dot4(m3, w1); v[14] = dot4(m3, w2); v[15] = dot4(m3, w3);
}

// Per-iteration statistics. sRedM: Mnum[c][0..15], Rsum at [c][16] (stride 17).
// sRedS: S1 at [c*33 + k], S2 at [c*33 + 16 + k] (stride 33, conflict-free).
__device__ __forceinline__ void compute_stats(
    const float* __restrict__ sRedM, const float* __restrict__ sRedS,
    int c, float rscale, float bv, float ba, float inv_temp,
    float M[16], float wgt[16], float& base, float& aj)
{
    float RsRaw = sRedM[c * 17 + 16];
    float Rs = RsRaw * rscale;               // rscale folds the uniform R=1/NC of iter 0
    float invR = 1.0f / RsRaw;
    float sumlog = 0.0f;
    #pragma unroll
    for (int k = 0; k < 16; k++) {
        float m   = sRedM[c * 17 + k] * invR;
        float s1  = sRedS[c * 33 + k];
        float s2  = sRedS[c * 33 + 16 + k];
        float var = s2 - 2.0f * m * s1 + 288.0f * m * m;
        var = fmaxf(var, 0.0f);
        float sd = sqrtf(var);
        sumlog += logf(sd + EPSV);
        wgt[k] = 0.5f / (sd * sd);           // 1/(2*stdv^2)
        M[k]   = m;
    }
    float cost = (16.0f * bv + sumlog) * Rs;
    float s = cost;
    #pragma unroll
    for (int o = 16; o >= 1; o >>= 1) s += __shfl_xor_sync(0xffffffffu, s, o);
    float cmean = s * (1.0f / 32.0f);
    float d = cost - cmean;
    float sq = d * d;
    #pragma unroll
    for (int o = 16; o >= 1; o >>= 1) sq += __shfl_xor_sync(0xffffffffu, sq, o);
    float cstd  = sqrtf(sq * (1.0f / 32.0f));
    float acost = ba + (cmean - cost) / (cstd + EPSV);
    aj   = 1.0f / (1.0f + expf(-inv_temp * acost));
    base = logf(aj + EPSV) - sumlog;
}

__global__ __launch_bounds__(NTH, 2)
void caps_em_kernel(const float* __restrict__ x,
                    const float* __restrict__ beta_v,
                    const float* __restrict__ beta_a,
                    float* __restrict__ out)
{
    __shared__ float sMp[KKI * 16];          // 4608 floats
    __shared__ float sA[KKI];                // 288
    __shared__ float sPart[NWARP * NC * 17]; // 4352 (per-warp staging, stride 17)
    __shared__ float sRedM[NC * 17];         // 544
    __shared__ float sRedS[NC * 33];         // 1056

    const int tid  = threadIdx.x;
    const int lane = tid & 31;        // capsule c
    const int wid  = tid >> 5;
    const int c    = lane;
    const int pos  = blockIdx.x;
    const int b  = pos / 144;
    const int rp = pos % 144;
    const int ho = rp / 12, wo = rp % 12;

    // ---- load patch: i = (ki*3+kj)*32 + cin ----
    for (int i = tid; i < KKI; i += NTH) {
        int kk = i >> 5, cin = i & 31;
        int ki = kk / 3, kj = kk % 3;
        const float* src = x + ((((b * 14) + ho + ki) * 14 + (wo + kj)) * 32 + cin) * 17;
        #pragma unroll
        for (int e = 0; e < 16; e++) sMp[i * 16 + e] = src[e];
        sA[i] = src[16];
    }
    __syncthreads();

    const float bv = beta_v[c];
    const float ba = beta_a[c];
    const int i0 = wid * IPW, i1 = i0 + IPW;
    float* myP = sPart + (wid * NC + c) * 17;

    // ================= PASS 1: iter 0 (uniform R) + S1/S2 =================
    {
        float Mnum[16], S1[16], S2[16];
        float Rsum = 0.0f;
        #pragma unroll
        for (int k = 0; k < 16; k++) { Mnum[k] = 0.0f; S1[k] = 0.0f; S2[k] = 0.0f; }
        #pragma unroll 2
        for (int i = i0; i < i1; i++) {
            float v[16];
            compute_v(sMp, i, c, v);
            float ai = sA[i];
            #pragma unroll
            for (int k = 0; k < 16; k++) {
                S1[k] += v[k];
                S2[k]  = fmaf(v[k], v[k], S2[k]);
                Mnum[k] = fmaf(ai, v[k], Mnum[k]);
            }
            Rsum += ai;
        }
        // --- round A: Mnum + Rsum ---
        #pragma unroll
        for (int k = 0; k < 16; k++) myP[k] = Mnum[k];
        myP[16] = Rsum;
        __syncthreads();
        for (int s = tid; s < NC * 17; s += NTH) {
            float acc = 0.0f;
            #pragma unroll
            for (int w = 0; w < NWARP; w++) acc += sPart[w * (NC * 17) + s];
            sRedM[s] = acc;
        }
        __syncthreads();
        // --- round B: S1 ---
        #pragma unroll
        for (int k = 0; k < 16; k++) myP[k] = S1[k];
        __syncthreads();
        for (int s = tid; s < NC * 17; s += NTH) {
            int cc = s / 17, kk = s - cc * 17;
            if (kk < 16) {
                float acc = 0.0f;
                #pragma unroll
                for (int w = 0; w < NWARP; w++) acc += sPart[w * (NC * 17) + s];
                sRedS[cc * 33 + kk] = acc;
            }
        }
        __syncthreads();
        // --- round C: S2 ---
        #pragma unroll
        for (int k = 0; k < 16; k++) myP[k] = S2[k];
        __syncthreads();
        for (int s = tid; s < NC * 17; s += NTH) {
            int cc = s / 17, kk = s - cc * 17;
            if (kk < 16) {
                float acc = 0.0f;
                #pragma unroll
                for (int w = 0; w < NWARP; w++) acc += sPart[w * (NC * 17) + s];
                sRedS[cc * 33 + 16 + kk] = acc;
            }
        }
        __syncthreads();
    }

    float M[16], wgt[16], base, aj;
    compute_stats(sRedM, sRedS, c, 1.0f / 32.0f, bv, ba, 1.0f, M, wgt, base, aj);

    // ================= PASS 2 & 3: routing iterations 1, 2 =================
    #pragma unroll 1
    for (int it = 1; it <= 2; it++) {
        float Mnum[16];
        float Rsum = 0.0f;
        #pragma unroll
        for (int k = 0; k < 16; k++) Mnum[k] = 0.0f;

        #pragma unroll 2
        for (int i = i0; i < i1; i++) {
            float v[16];
            compute_v(sMp, i, c, v);
            float e = 0.0f;
            #pragma unroll
            for (int k = 0; k < 16; k++) {
                float d = v[k] - M[k];
                e = fmaf(d * wgt[k], d, e);
            }
            float lp = base - e;
            // softmax over capsules (lanes)
            float mx = lp;
            #pragma unroll
            for (int o = 16; o >= 1; o >>= 1) mx = fmaxf(mx, __shfl_xor_sync(0xffffffffu, mx, o));
            float ex = __expf(lp - mx);
            float sm = ex;
            #pragma unroll
            for (int o = 16; o >= 1; o >>= 1) sm += __shfl_xor_sync(0xffffffffu, sm, o);
            float Rw = sA[i] * __fdividef(ex, sm);
            Rsum += Rw;
            #pragma unroll
            for (int k = 0; k < 16; k++) Mnum[k] = fmaf(Rw, v[k], Mnum[k]);
        }
        __syncthreads();  // protect sPart reuse from previous round's readers
        #pragma unroll
        for (int k = 0; k < 16; k++) myP[k] = Mnum[k];
        myP[16] = Rsum;
        __syncthreads();
        for (int s = tid; s < NC * 17; s += NTH) {
            float acc = 0.0f;
            #pragma unroll
            for (int w = 0; w < NWARP; w++) acc += sPart[w * (NC * 17) + s];
            sRedM[s] = acc;
        }
        __syncthreads();

        compute_stats(sRedM, sRedS, c, 1.0f, bv, ba, 1.0f + (float)it, M, wgt, base, aj);
    }

    // ---- write output: [pos][c][0..15] = M, [16] = sigmoid(a_j) ----
    if (wid == 0) {
        float* dst = out + (pos * NC + c) * 17;
        #pragma unroll
        for (int k = 0; k < 16; k++) dst[k] = M[k];
        dst[16] = 1.0f / (1.0f + expf(-aj));
    }
}

extern "C" void kernel_launch(void* const* d_in, const int* in_sizes, int n_in,
                              void* d_out, int out_size) {
    const float* x      = (const float*)d_in[0];
    const float* W      = (const float*)d_in[1];
    const float* beta_v = (const float*)d_in[2];
    const float* beta_a = (const float*)d_in[3];
    float* out = (float*)d_out;

    relayout_W_kernel<<<(KKI * NC * PP + 255) / 256, 256>>>(W);
    caps_em_kernel<<<NPOS, NTH>>>(x, beta_v, beta_a, out);
}